// round 2
// baseline (speedup 1.0000x reference)
#include <cuda_runtime.h>
#include <math.h>

// ---------------- Problem constants ----------------
#define B_    4
#define S_    2048
#define T_    8192          // B*S tokens
#define D_    1024          // d_model
#define DFF_  4096
#define E_    8
#define TOPK_ 2
#define CAP_  1024          // CAP_FACTOR * T / E

// ---------------- Device scratch (static; no allocations allowed) ----------------
__device__ float g_xg[(size_t)E_ * CAP_ * D_];       // gathered expert inputs   (32 MB)
__device__ float g_h [(size_t)E_ * CAP_ * DFF_];     // hidden activations      (128 MB)
__device__ float g_y [(size_t)E_ * CAP_ * D_];       // expert outputs           (32 MB)
__device__ int   g_tokens[E_ * CAP_];                // per-expert token list
__device__ float g_gates [E_ * CAP_];                // per-slot combine weight (0 for pad)
__device__ int   g_te0[T_], g_te1[T_];               // per-token top-2 expert ids
__device__ float g_tw0[T_], g_tw1[T_];               // per-token normalized weights
__device__ int   g_tslot[2 * T_];                    // token -> slot (e*CAP+c) or -1
__device__ int   g_counts[E_];                       // full assignment counts (for lb loss)

// ---------------- Router: logits, 2-way softmax over top-2, tie rules match top_k ----------------
__global__ void __launch_bounds__(256) router_kernel(
    const float* __restrict__ x, const float* __restrict__ rw)
{
    __shared__ float srw[E_ * D_];   // 32 KB router weights
    int tid = threadIdx.x;
    for (int i = tid; i < E_ * D_; i += 256) srw[i] = rw[i];
    __syncthreads();

    int warp = tid >> 5, lane = tid & 31;
    int t = blockIdx.x * 8 + warp;
    const float* xt = x + (size_t)t * D_;

    float acc[E_];
#pragma unroll
    for (int e = 0; e < E_; e++) acc[e] = 0.f;

    for (int c = 0; c < D_ / 32; c++) {
        float xv = xt[c * 32 + lane];
#pragma unroll
        for (int e = 0; e < E_; e++)
            acc[e] += xv * srw[e * D_ + c * 32 + lane];
    }
#pragma unroll
    for (int e = 0; e < E_; e++) {
#pragma unroll
        for (int off = 16; off; off >>= 1)
            acc[e] += __shfl_xor_sync(0xffffffffu, acc[e], off);
    }
    if (lane == 0) {
        // top-2 on logits (monotone with softmax probs); ties -> lower index first
        int b0 = 0; float v0 = acc[0];
#pragma unroll
        for (int e = 1; e < E_; e++) if (acc[e] > v0) { v0 = acc[e]; b0 = e; }
        int b1 = -1; float v1 = -INFINITY;
#pragma unroll
        for (int e = 0; e < E_; e++) if (e != b0 && acc[e] > v1) { v1 = acc[e]; b1 = e; }
        // vals/sum(vals) over top-2 probs == 2-way softmax over top-2 logits
        float ex = expf(v1 - v0);          // <= 1
        float w0 = 1.f / (1.f + ex);
        float w1 = ex * w0;
        g_te0[t] = b0; g_te1[t] = b1;
        g_tw0[t] = w0; g_tw1[t] = w1;
        g_tslot[2 * t + 0] = -1;
        g_tslot[2 * t + 1] = -1;
    }
}

// ---------------- Capacity-limited dispatch: ordered block scan per expert ----------------
__global__ void __launch_bounds__(256) dispatch_kernel()
{
    int e = blockIdx.x;
    int tid = threadIdx.x;
    int lane = tid & 31, warp = tid >> 5;
    __shared__ int warpsums[8];

    // pad slots (handles count < capacity; gate 0 => no contribution)
    for (int c = tid; c < CAP_; c += 256) { g_tokens[e * CAP_ + c] = 0; g_gates[e * CAP_ + c] = 0.f; }
    __syncthreads();

    int running = 0;
    for (int it = 0; it < T_ / 256; ++it) {
        int t = it * 256 + tid;
        int which = (g_te0[t] == e) ? 0 : ((g_te1[t] == e) ? 1 : -1);
        int flag = (which >= 0) ? 1 : 0;

        // warp inclusive scan
        int v = flag;
#pragma unroll
        for (int off = 1; off < 32; off <<= 1) {
            int n = __shfl_up_sync(0xffffffffu, v, off);
            if (lane >= off) v += n;
        }
        if (lane == 31) warpsums[warp] = v;
        __syncthreads();

        int woff = 0, total = 0;
#pragma unroll
        for (int w = 0; w < 8; w++) {
            int s = warpsums[w];
            if (w < warp) woff += s;
            total += s;
        }
        int slot = running + woff + v - flag;   // exclusive prefix in token order
        if (flag && slot < CAP_) {
            g_tokens[e * CAP_ + slot] = t;
            g_gates [e * CAP_ + slot] = which ? g_tw1[t] : g_tw0[t];
            g_tslot[2 * t + which] = e * CAP_ + slot;
        }
        running += total;
        __syncthreads();
    }
    if (tid == 0) g_counts[e] = running;   // full count (pre-capacity) for lb loss
}

// ---------------- Gather rows for the grouped GEMM ----------------
__global__ void __launch_bounds__(256) gather_kernel(const float* __restrict__ x)
{
    int row = blockIdx.x;                       // e*CAP + c
    int t = g_tokens[row];
    const float4* src = (const float4*)(x + (size_t)t * D_);
    float4* dst = (float4*)(g_xg + (size_t)row * D_);
    dst[threadIdx.x] = src[threadIdx.x];        // 256 * float4 = 1024 floats
}

// ---------------- Tiled fp32 GEMM: C = act(A@B + bias), batched over experts ----------------
__device__ __forceinline__ float gelu_exact(float v) {
    return 0.5f * v * (1.f + erff(v * 0.70710678118654752f));
}

template<bool GELU>
__global__ void __launch_bounds__(256) gemm_bias_kernel(
    const float* __restrict__ A, const float* __restrict__ B,
    const float* __restrict__ bias, float* __restrict__ C,
    int M, int N, int Kd)
{
    const int BM = 128, BN = 128, BK = 16;
    __shared__ float As[BK][BM];
    __shared__ float Bs[BK][BN];

    int e = blockIdx.z;
    const float* Ab   = A    + (size_t)e * M * Kd;
    const float* Bb   = B    + (size_t)e * Kd * N;
    const float* bb   = bias + (size_t)e * N;
    float*       Cb   = C    + (size_t)e * M * N;

    int tid = threadIdx.x;
    int tx = tid & 15, ty = tid >> 4;
    int rowBase = blockIdx.y * BM;
    int colBase = blockIdx.x * BN;

    float acc[8][8];
#pragma unroll
    for (int i = 0; i < 8; i++)
#pragma unroll
        for (int j = 0; j < 8; j++) acc[i][j] = 0.f;

    for (int k0 = 0; k0 < Kd; k0 += BK) {
        // A tile: 128 rows x 16 cols, stored transposed
#pragma unroll
        for (int i = 0; i < 2; i++) {
            int idx = tid + i * 256;             // 0..511 float4 slots
            int r = idx >> 2, c4 = idx & 3;
            float4 v = *(const float4*)&Ab[(size_t)(rowBase + r) * Kd + k0 + c4 * 4];
            As[c4 * 4 + 0][r] = v.x; As[c4 * 4 + 1][r] = v.y;
            As[c4 * 4 + 2][r] = v.z; As[c4 * 4 + 3][r] = v.w;
        }
        // B tile: 16 rows x 128 cols
#pragma unroll
        for (int i = 0; i < 2; i++) {
            int idx = tid + i * 256;
            int r = idx >> 5, c4 = idx & 31;
            float4 v = *(const float4*)&Bb[(size_t)(k0 + r) * N + colBase + c4 * 4];
            *(float4*)&Bs[r][c4 * 4] = v;
        }
        __syncthreads();

#pragma unroll
        for (int k = 0; k < BK; k++) {
            float a[8], b[8];
            float4 a0 = *(const float4*)&As[k][ty * 8];
            float4 a1 = *(const float4*)&As[k][ty * 8 + 4];
            a[0]=a0.x; a[1]=a0.y; a[2]=a0.z; a[3]=a0.w;
            a[4]=a1.x; a[5]=a1.y; a[6]=a1.z; a[7]=a1.w;
            float4 b0 = *(const float4*)&Bs[k][tx * 8];
            float4 b1 = *(const float4*)&Bs[k][tx * 8 + 4];
            b[0]=b0.x; b[1]=b0.y; b[2]=b0.z; b[3]=b0.w;
            b[4]=b1.x; b[5]=b1.y; b[6]=b1.z; b[7]=b1.w;
#pragma unroll
            for (int i = 0; i < 8; i++)
#pragma unroll
                for (int j = 0; j < 8; j++)
                    acc[i][j] += a[i] * b[j];
        }
        __syncthreads();
    }

#pragma unroll
    for (int i = 0; i < 8; i++) {
        int row = rowBase + ty * 8 + i;
#pragma unroll
        for (int j4 = 0; j4 < 2; j4++) {
            int col = colBase + tx * 8 + j4 * 4;
            float4 bv = *(const float4*)&bb[col];
            float4 o;
            o.x = acc[i][j4 * 4 + 0] + bv.x;
            o.y = acc[i][j4 * 4 + 1] + bv.y;
            o.z = acc[i][j4 * 4 + 2] + bv.z;
            o.w = acc[i][j4 * 4 + 3] + bv.w;
            if (GELU) {
                o.x = gelu_exact(o.x); o.y = gelu_exact(o.y);
                o.z = gelu_exact(o.z); o.w = gelu_exact(o.w);
            }
            *(float4*)&Cb[(size_t)row * N + col] = o;
        }
    }
}

// ---------------- Combine: gather each token's <=2 weighted expert outputs ----------------
__global__ void __launch_bounds__(256) combine_kernel(float* __restrict__ out)
{
    int t = blockIdx.x;
    int p0 = g_tslot[2 * t], p1 = g_tslot[2 * t + 1];
    int i = threadIdx.x;
    float4 r = make_float4(0.f, 0.f, 0.f, 0.f);
    if (p0 >= 0) {
        float w = g_gates[p0];
        float4 a = ((const float4*)(g_y + (size_t)p0 * D_))[i];
        r.x += w * a.x; r.y += w * a.y; r.z += w * a.z; r.w += w * a.w;
    }
    if (p1 >= 0) {
        float w = g_gates[p1];
        float4 a = ((const float4*)(g_y + (size_t)p1 * D_))[i];
        r.x += w * a.x; r.y += w * a.y; r.z += w * a.z; r.w += w * a.w;
    }
    ((float4*)(out + (size_t)t * D_))[i] = r;
}

// ---------------- Load-balancing loss ----------------
__global__ void loss_kernel(float* __restrict__ loss_out)
{
    if (threadIdx.x == 0) {
        const float ideal = (float)T_ * TOPK_ / E_;   // 2048
        float s = 0.f;
#pragma unroll
        for (int e = 0; e < E_; e++) {
            float d = (float)g_counts[e] - ideal;
            s += d * d;
        }
        *loss_out = s / ((float)T_ * (float)T_);
    }
}

// ---------------- Launch ----------------
extern "C" void kernel_launch(void* const* d_in, const int* in_sizes, int n_in,
                              void* d_out, int out_size)
{
    const float* x  = (const float*)d_in[0];   // [B,S,D]
    const float* rw = (const float*)d_in[1];   // [E,D]
    const float* w1 = (const float*)d_in[2];   // [E,D,DFF]
    const float* b1 = (const float*)d_in[3];   // [E,DFF]
    const float* w2 = (const float*)d_in[4];   // [E,DFF,D]
    const float* b2 = (const float*)d_in[5];   // [E,D]
    float* out = (float*)d_out;

    float* xg; cudaGetSymbolAddress((void**)&xg, g_xg);
    float* h;  cudaGetSymbolAddress((void**)&h,  g_h);
    float* y;  cudaGetSymbolAddress((void**)&y,  g_y);

    router_kernel<<<T_ / 8, 256>>>(x, rw);
    dispatch_kernel<<<E_, 256>>>();
    gather_kernel<<<E_ * CAP_, 256>>>(x);
    gemm_bias_kernel<true ><<<dim3(DFF_ / 128, CAP_ / 128, E_), 256>>>(xg, w1, b1, h, CAP_, DFF_, D_);
    gemm_bias_kernel<false><<<dim3(D_   / 128, CAP_ / 128, E_), 256>>>(h,  w2, b2, y, CAP_, D_,  DFF_);
    combine_kernel<<<T_, 256>>>(out);
    loss_kernel<<<1, 32>>>(out + (out_size - 1));
}

// round 4
// speedup vs baseline: 2.0840x; 2.0840x over previous
#include <cuda_runtime.h>
#include <cuda_bf16.h>
#include <math.h>
#include <stdint.h>

// ---------------- Problem constants ----------------
#define B_    4
#define S_    2048
#define T_    8192          // B*S tokens
#define D_    1024          // d_model
#define DFF_  4096
#define E_    8
#define TOPK_ 2
#define CAP_  1024          // CAP_FACTOR * T / E

#define KP1   (3*D_)        // 3072  (split-K for GEMM1)
#define KP2   (3*DFF_)      // 12288 (split-K for GEMM2)

// ---------------- Device scratch (static; no allocations allowed) ----------------
__device__ __nv_bfloat16 g_xg3[(size_t)E_ * CAP_ * KP1];   // 50 MB  A of GEMM1 (h,h,l)
__device__ __nv_bfloat16 g_w1b[(size_t)E_ * DFF_ * KP1];   // 201 MB B of GEMM1 (H,L,H)
__device__ __nv_bfloat16 g_w2b[(size_t)E_ * D_   * KP2];   // 201 MB B of GEMM2 (H,L,H)
__device__ __nv_bfloat16 g_h3 [(size_t)E_ * CAP_ * KP2];   // 201 MB A of GEMM2 (h,h,l)
__device__ float g_y[(size_t)E_ * CAP_ * D_];              // expert outputs fp32
__device__ int   g_tokens[E_ * CAP_];
__device__ float g_gates [E_ * CAP_];
__device__ int   g_te0[T_], g_te1[T_];
__device__ float g_tw0[T_], g_tw1[T_];
__device__ int   g_tslot[2 * T_];
__device__ int   g_counts[E_];

// ---------------- helpers ----------------
#define CP_ASYNC16(sa, ga) \
    asm volatile("cp.async.cg.shared.global [%0], [%1], 16;" :: "r"(sa), "l"(ga))
#define CP_COMMIT()  asm volatile("cp.async.commit_group;")
#define CP_WAIT1()   asm volatile("cp.async.wait_group 1;")
#define SWZ(o) ((o) ^ ((((uint32_t)(o)) >> 3) & 0x70))

#define LDMATRIX_X4(f, a) \
    asm volatile("ldmatrix.sync.aligned.m8n8.x4.shared.b16 {%0,%1,%2,%3}, [%4];" \
        : "=r"((f)[0]), "=r"((f)[1]), "=r"((f)[2]), "=r"((f)[3]) : "r"(a))

#define MMA_16816(c, a, b0, b1) \
    asm volatile("mma.sync.aligned.m16n8k16.row.col.f32.bf16.bf16.f32 " \
        "{%0,%1,%2,%3}, {%4,%5,%6,%7}, {%8,%9}, {%0,%1,%2,%3};" \
        : "+f"((c)[0]), "+f"((c)[1]), "+f"((c)[2]), "+f"((c)[3]) \
        : "r"((a)[0]), "r"((a)[1]), "r"((a)[2]), "r"((a)[3]), "r"(b0), "r"(b1))

// ---------------- Router ----------------
__global__ void __launch_bounds__(256) router_kernel(
    const float* __restrict__ x, const float* __restrict__ rw)
{
    __shared__ float srw[E_ * D_];
    int tid = threadIdx.x;
    for (int i = tid; i < E_ * D_; i += 256) srw[i] = rw[i];
    __syncthreads();

    int warp = tid >> 5, lane = tid & 31;
    int t = blockIdx.x * 8 + warp;
    const float* xt = x + (size_t)t * D_;

    float acc[E_];
#pragma unroll
    for (int e = 0; e < E_; e++) acc[e] = 0.f;
    for (int c = 0; c < D_ / 32; c++) {
        float xv = xt[c * 32 + lane];
#pragma unroll
        for (int e = 0; e < E_; e++)
            acc[e] += xv * srw[e * D_ + c * 32 + lane];
    }
#pragma unroll
    for (int e = 0; e < E_; e++) {
#pragma unroll
        for (int off = 16; off; off >>= 1)
            acc[e] += __shfl_xor_sync(0xffffffffu, acc[e], off);
    }
    if (lane == 0) {
        int b0 = 0; float v0 = acc[0];
#pragma unroll
        for (int e = 1; e < E_; e++) if (acc[e] > v0) { v0 = acc[e]; b0 = e; }
        int b1 = -1; float v1 = -INFINITY;
#pragma unroll
        for (int e = 0; e < E_; e++) if (e != b0 && acc[e] > v1) { v1 = acc[e]; b1 = e; }
        float ex = expf(v1 - v0);
        float w0 = 1.f / (1.f + ex);
        float w1 = ex * w0;
        g_te0[t] = b0; g_te1[t] = b1;
        g_tw0[t] = w0; g_tw1[t] = w1;
        g_tslot[2 * t + 0] = -1;
        g_tslot[2 * t + 1] = -1;
    }
}

// ---------------- Dispatch (ordered capacity scan) ----------------
__global__ void __launch_bounds__(256) dispatch_kernel()
{
    int e = blockIdx.x;
    int tid = threadIdx.x;
    int lane = tid & 31, warp = tid >> 5;
    __shared__ int warpsums[8];

    for (int c = tid; c < CAP_; c += 256) { g_tokens[e * CAP_ + c] = 0; g_gates[e * CAP_ + c] = 0.f; }
    __syncthreads();

    int running = 0;
    for (int it = 0; it < T_ / 256; ++it) {
        int t = it * 256 + tid;
        int which = (g_te0[t] == e) ? 0 : ((g_te1[t] == e) ? 1 : -1);
        int flag = (which >= 0) ? 1 : 0;

        int v = flag;
#pragma unroll
        for (int off = 1; off < 32; off <<= 1) {
            int n = __shfl_up_sync(0xffffffffu, v, off);
            if (lane >= off) v += n;
        }
        if (lane == 31) warpsums[warp] = v;
        __syncthreads();

        int woff = 0, total = 0;
#pragma unroll
        for (int w = 0; w < 8; w++) {
            int s = warpsums[w];
            if (w < warp) woff += s;
            total += s;
        }
        int slot = running + woff + v - flag;
        if (flag && slot < CAP_) {
            g_tokens[e * CAP_ + slot] = t;
            g_gates [e * CAP_ + slot] = which ? g_tw1[t] : g_tw0[t];
            g_tslot[2 * t + which] = e * CAP_ + slot;
        }
        running += total;
        __syncthreads();
    }
    if (tid == 0) g_counts[e] = running;
}

// ---------------- Gather + 3-term bf16 split (A pattern h,h,l) ----------------
__global__ void __launch_bounds__(256) gather_split_kernel(const float* __restrict__ x)
{
    int row = blockIdx.x;                       // e*CAP + c
    int t = g_tokens[row];
    int tid = threadIdx.x;
    float4 v = ((const float4*)(x + (size_t)t * D_))[tid];
    float vv[4] = {v.x, v.y, v.z, v.w};
    unsigned short s[12];
#pragma unroll
    for (int j = 0; j < 4; j++) {
        __nv_bfloat16 hb = __float2bfloat16_rn(vv[j]);
        __nv_bfloat16 lb = __float2bfloat16_rn(vv[j] - __bfloat162float(hb));
        unsigned short h = __bfloat16_as_ushort(hb);
        unsigned short l = __bfloat16_as_ushort(lb);
        s[3*j] = h; s[3*j+1] = h; s[3*j+2] = l;
    }
    uint2* dst = (uint2*)(g_xg3 + (size_t)row * KP1 + 12 * tid);
    uint2 a, b, c2;
    a.x  = (uint32_t)s[0] | ((uint32_t)s[1] << 16);
    a.y  = (uint32_t)s[2] | ((uint32_t)s[3] << 16);
    b.x  = (uint32_t)s[4] | ((uint32_t)s[5] << 16);
    b.y  = (uint32_t)s[6] | ((uint32_t)s[7] << 16);
    c2.x = (uint32_t)s[8] | ((uint32_t)s[9] << 16);
    c2.y = (uint32_t)s[10]| ((uint32_t)s[11]<< 16);
    dst[0] = a; dst[1] = b; dst[2] = c2;
}

// ---------------- Weight transpose + split: [E,K,N] fp32 -> [E,N,3K] bf16 (H,L,H) ----------------
__global__ void __launch_bounds__(256) convert_w_kernel(
    const float* __restrict__ src, __nv_bfloat16* __restrict__ dst, int K, int N)
{
    __shared__ float tile[32][33];
    int e = blockIdx.z;
    int k0 = blockIdx.y * 32, n0 = blockIdx.x * 32;
    int tx = threadIdx.x, ty = threadIdx.y;     // (32,8)
    const float* se = src + (size_t)e * K * N;
    __nv_bfloat16* de = dst + (size_t)e * N * 3 * K;
#pragma unroll
    for (int i = 0; i < 4; i++)
        tile[ty + 8*i][tx] = se[(size_t)(k0 + ty + 8*i) * N + n0 + tx];
    __syncthreads();
#pragma unroll
    for (int i = 0; i < 4; i++) {
        int n = n0 + ty + 8*i, k = k0 + tx;
        float v = tile[tx][ty + 8*i];
        __nv_bfloat16 hb = __float2bfloat16_rn(v);
        __nv_bfloat16 lb = __float2bfloat16_rn(v - __bfloat162float(hb));
        __nv_bfloat16* p = de + (size_t)n * 3 * K + 3 * k;
        p[0] = hb; p[1] = lb; p[2] = hb;        // B pattern H,L,H
    }
}

// ---------------- HMMA grouped GEMM: out = act(A @ B^T + bias) ----------------
// A: [M, Kp] bf16 K-major per expert. B: [Nt, Kp] bf16 K-major per expert.
// CTA tile 128x256x64, 512 threads (16 warps 4x4), warp tile 32x64, 3-stage cp.async.
__device__ __forceinline__ float gelu_exact(float v) {
    return 0.5f * v * (1.f + erff(v * 0.70710678118654752f));
}

#define STAGE_BYTES 49152           // 16KB A + 32KB B
#define SMEM_BYTES_GEMM (3 * STAGE_BYTES)

template<bool GELU_SPLIT>
__global__ void __launch_bounds__(512, 1) gemm_mma_kernel(
    const __nv_bfloat16* __restrict__ A, const __nv_bfloat16* __restrict__ Bw,
    const float* __restrict__ bias, void* __restrict__ outv,
    int M, int Nt, int Kp)
{
    extern __shared__ char smem[];
    uint32_t sb = (uint32_t)__cvta_generic_to_shared(smem);

    int tid  = threadIdx.x;
    int lane = tid & 31;
    int warp = tid >> 5;
    int wm = warp >> 2, wn = warp & 3;          // 4x4 warp grid

    int e  = blockIdx.z;
    int n0 = blockIdx.x * 256, m0 = blockIdx.y * 128;

    const char* Ae = (const char*)(A  + (size_t)e * M  * Kp + (size_t)m0 * Kp);
    const char* Be = (const char*)(Bw + (size_t)e * Nt * Kp + (size_t)n0 * Kp);
    const float* be = bias + (size_t)e * Nt;
    const size_t ld = (size_t)Kp * 2;           // row stride in bytes

    const int NCH = Kp / 64;                    // 128B chunks along K

    // stage loader: chunk c into stage s
    auto load_stage = [&](int c, int s) {
        const char* Ag = Ae + (size_t)c * 128;
        const char* Bg = Be + (size_t)c * 128;
        uint32_t Aoff = sb + s * STAGE_BYTES;
        uint32_t Boff = Aoff + 16384;
#pragma unroll 2
        for (int i = tid; i < 1024; i += 512) {         // A: 128 rows x 8 x 16B
            int r = i >> 3, c16 = i & 7;
            CP_ASYNC16(Aoff + SWZ(r * 128 + c16 * 16), Ag + (size_t)r * ld + c16 * 16);
        }
#pragma unroll 4
        for (int i = tid; i < 2048; i += 512) {         // B: 256 rows x 8 x 16B
            int r = i >> 3, c16 = i & 7;
            CP_ASYNC16(Boff + SWZ(r * 128 + c16 * 16), Bg + (size_t)r * ld + c16 * 16);
        }
    };

    float acc[2][8][4];
#pragma unroll
    for (int i = 0; i < 2; i++)
#pragma unroll
        for (int j = 0; j < 8; j++)
#pragma unroll
            for (int k = 0; k < 4; k++) acc[i][j][k] = 0.f;

    load_stage(0, 0); CP_COMMIT();
    load_stage(1, 1); CP_COMMIT();

    int aRow = wm * 32 + (lane & 15);
    int bRow = wn * 64 + (lane & 15);
    int halfCol = (lane >> 4) * 16;             // 16B column offset for ldmatrix

    for (int c = 0; c < NCH; ++c) {
        CP_WAIT1();
        __syncthreads();
        if (c + 2 < NCH) load_stage(c + 2, (c + 2) % 3);
        CP_COMMIT();

        int s = c % 3;
        uint32_t Aoff = sb + s * STAGE_BYTES;
        uint32_t Boff = Aoff + 16384;

#pragma unroll
        for (int ks = 0; ks < 4; ks++) {
            uint32_t afr[2][4], bfr[4][4];
#pragma unroll
            for (int mt = 0; mt < 2; mt++) {
                uint32_t ad = Aoff + SWZ((aRow + mt * 16) * 128 + ks * 32 + halfCol);
                LDMATRIX_X4(afr[mt], ad);
            }
#pragma unroll
            for (int nt = 0; nt < 4; nt++) {
                uint32_t bd = Boff + SWZ((bRow + nt * 16) * 128 + ks * 32 + halfCol);
                LDMATRIX_X4(bfr[nt], bd);
            }
#pragma unroll
            for (int mt = 0; mt < 2; mt++)
#pragma unroll
                for (int n8 = 0; n8 < 8; n8++) {
                    int nt = n8 >> 1, j = n8 & 1;
                    MMA_16816(acc[mt][n8], afr[mt], bfr[nt][j], bfr[nt][2 + j]);
                }
        }
        __syncthreads();
    }

    // -------- Epilogue --------
#pragma unroll
    for (int mt = 0; mt < 2; mt++) {
#pragma unroll
        for (int rr = 0; rr < 2; rr++) {
            int row = m0 + wm * 32 + mt * 16 + (lane >> 2) + rr * 8;
#pragma unroll
            for (int n8 = 0; n8 < 8; n8++) {
                int colL = wn * 64 + n8 * 8 + (lane & 3) * 2;
                int col  = n0 + colL;
                float v0 = acc[mt][n8][rr * 2 + 0] + be[col];
                float v1 = acc[mt][n8][rr * 2 + 1] + be[col + 1];
                if (GELU_SPLIT) {
                    v0 = gelu_exact(v0); v1 = gelu_exact(v1);
                    __nv_bfloat16 h0b = __float2bfloat16_rn(v0);
                    __nv_bfloat16 l0b = __float2bfloat16_rn(v0 - __bfloat162float(h0b));
                    __nv_bfloat16 h1b = __float2bfloat16_rn(v1);
                    __nv_bfloat16 l1b = __float2bfloat16_rn(v1 - __bfloat162float(h1b));
                    uint32_t h0 = __bfloat16_as_ushort(h0b), l0 = __bfloat16_as_ushort(l0b);
                    uint32_t h1 = __bfloat16_as_ushort(h1b), l1 = __bfloat16_as_ushort(l1b);
                    __nv_bfloat16* oe = (__nv_bfloat16*)outv
                        + (size_t)e * M * 3 * Nt + (size_t)row * 3 * Nt + (size_t)3 * col;
                    uint32_t* p = (uint32_t*)oe;        // 12B-aligned (col even)
                    p[0] = h0 | (h0 << 16);             // h0,h0
                    p[1] = l0 | (h1 << 16);             // l0,h1
                    p[2] = h1 | (l1 << 16);             // h1,l1
                } else {
                    float* oe = (float*)outv + (size_t)e * M * Nt + (size_t)row * Nt + col;
                    *(float2*)oe = make_float2(v0, v1);
                }
            }
        }
    }
}

// ---------------- Combine ----------------
__global__ void __launch_bounds__(256) combine_kernel(float* __restrict__ out)
{
    int t = blockIdx.x;
    int p0 = g_tslot[2 * t], p1 = g_tslot[2 * t + 1];
    int i = threadIdx.x;
    float4 r = make_float4(0.f, 0.f, 0.f, 0.f);
    if (p0 >= 0) {
        float w = g_gates[p0];
        float4 a = ((const float4*)(g_y + (size_t)p0 * D_))[i];
        r.x += w * a.x; r.y += w * a.y; r.z += w * a.z; r.w += w * a.w;
    }
    if (p1 >= 0) {
        float w = g_gates[p1];
        float4 a = ((const float4*)(g_y + (size_t)p1 * D_))[i];
        r.x += w * a.x; r.y += w * a.y; r.z += w * a.z; r.w += w * a.w;
    }
    ((float4*)(out + (size_t)t * D_))[i] = r;
}

// ---------------- Load-balancing loss ----------------
__global__ void loss_kernel(float* __restrict__ loss_out)
{
    if (threadIdx.x == 0) {
        const float ideal = (float)T_ * TOPK_ / E_;
        float s = 0.f;
#pragma unroll
        for (int e = 0; e < E_; e++) {
            float d = (float)g_counts[e] - ideal;
            s += d * d;
        }
        *loss_out = s / ((float)T_ * (float)T_);
    }
}

// ---------------- Launch ----------------
extern "C" void kernel_launch(void* const* d_in, const int* in_sizes, int n_in,
                              void* d_out, int out_size)
{
    const float* x  = (const float*)d_in[0];
    const float* rw = (const float*)d_in[1];
    const float* w1 = (const float*)d_in[2];
    const float* b1 = (const float*)d_in[3];
    const float* w2 = (const float*)d_in[4];
    const float* b2 = (const float*)d_in[5];
    float* out = (float*)d_out;

    __nv_bfloat16 *xg3, *w1b, *w2b, *h3; float* y;
    cudaGetSymbolAddress((void**)&xg3, g_xg3);
    cudaGetSymbolAddress((void**)&w1b, g_w1b);
    cudaGetSymbolAddress((void**)&w2b, g_w2b);
    cudaGetSymbolAddress((void**)&h3,  g_h3);
    cudaGetSymbolAddress((void**)&y,   g_y);

    cudaFuncSetAttribute(gemm_mma_kernel<true>,
                         cudaFuncAttributeMaxDynamicSharedMemorySize, SMEM_BYTES_GEMM);
    cudaFuncSetAttribute(gemm_mma_kernel<false>,
                         cudaFuncAttributeMaxDynamicSharedMemorySize, SMEM_BYTES_GEMM);

    router_kernel<<<T_ / 8, 256>>>(x, rw);
    dispatch_kernel<<<E_, 256>>>();
    gather_split_kernel<<<E_ * CAP_, 256>>>(x);
    convert_w_kernel<<<dim3(DFF_ / 32, D_ / 32, E_), dim3(32, 8)>>>(w1, w1b, D_, DFF_);
    convert_w_kernel<<<dim3(D_ / 32, DFF_ / 32, E_), dim3(32, 8)>>>(w2, w2b, DFF_, D_);

    gemm_mma_kernel<true><<<dim3(DFF_ / 256, CAP_ / 128, E_), 512, SMEM_BYTES_GEMM>>>(
        xg3, w1b, b1, (void*)h3, CAP_, DFF_, KP1);
    gemm_mma_kernel<false><<<dim3(D_ / 256, CAP_ / 128, E_), 512, SMEM_BYTES_GEMM>>>(
        h3, w2b, b2, (void*)y, CAP_, D_, KP2);

    combine_kernel<<<T_, 256>>>(out);
    loss_kernel<<<1, 32>>>(out + (out_size - 1));
}

// round 5
// speedup vs baseline: 2.1174x; 1.0160x over previous
#include <cuda_runtime.h>
#include <cuda_bf16.h>
#include <math.h>
#include <stdint.h>

// ---------------- Problem constants ----------------
#define B_    4
#define S_    2048
#define T_    8192          // B*S tokens
#define D_    1024          // d_model
#define DFF_  4096
#define E_    8
#define TOPK_ 2
#define CAP_  1024          // CAP_FACTOR * T / E

#define KP1   (3*D_)        // 3072  (split-K for GEMM1)
#define KP2   (3*DFF_)      // 12288 (split-K for GEMM2)

// ---------------- Device scratch (static; no allocations allowed) ----------------
__device__ __nv_bfloat16 g_xg3[(size_t)E_ * CAP_ * KP1];   // 50 MB  A of GEMM1 (h,h,l)
__device__ __nv_bfloat16 g_w1b[(size_t)E_ * DFF_ * KP1];   // 201 MB B of GEMM1 (H,L,H)
__device__ __nv_bfloat16 g_w2b[(size_t)E_ * D_   * KP2];   // 201 MB B of GEMM2 (H,L,H)
__device__ __nv_bfloat16 g_h3 [(size_t)E_ * CAP_ * KP2];   // 201 MB A of GEMM2 (h,h,l)
__device__ float g_y[(size_t)E_ * CAP_ * D_];              // expert outputs fp32
__device__ int   g_tokens[E_ * CAP_];
__device__ float g_gates [E_ * CAP_];
__device__ int   g_te0[T_], g_te1[T_];
__device__ float g_tw0[T_], g_tw1[T_];
__device__ int   g_tslot[2 * T_];
__device__ int   g_counts[E_];

// ---------------- helpers ----------------
#define CP_ASYNC16(sa, ga) \
    asm volatile("cp.async.cg.shared.global [%0], [%1], 16;" :: "r"(sa), "l"(ga))
#define CP_COMMIT()  asm volatile("cp.async.commit_group;")
#define CP_WAIT2()   asm volatile("cp.async.wait_group 2;")
#define SWZ(o) ((o) ^ ((((uint32_t)(o)) >> 3) & 0x70))

#define LDMATRIX_X4(f, a) \
    asm volatile("ldmatrix.sync.aligned.m8n8.x4.shared.b16 {%0,%1,%2,%3}, [%4];" \
        : "=r"((f)[0]), "=r"((f)[1]), "=r"((f)[2]), "=r"((f)[3]) : "r"(a))

#define MMA_16816(c, a, b0, b1) \
    asm volatile("mma.sync.aligned.m16n8k16.row.col.f32.bf16.bf16.f32 " \
        "{%0,%1,%2,%3}, {%4,%5,%6,%7}, {%8,%9}, {%0,%1,%2,%3};" \
        : "+f"((c)[0]), "+f"((c)[1]), "+f"((c)[2]), "+f"((c)[3]) \
        : "r"((a)[0]), "r"((a)[1]), "r"((a)[2]), "r"((a)[3]), "r"(b0), "r"(b1))

// ---------------- Router ----------------
__global__ void __launch_bounds__(256) router_kernel(
    const float* __restrict__ x, const float* __restrict__ rw)
{
    __shared__ float srw[E_ * D_];
    int tid = threadIdx.x;
    for (int i = tid; i < E_ * D_; i += 256) srw[i] = rw[i];
    __syncthreads();

    int warp = tid >> 5, lane = tid & 31;
    int t = blockIdx.x * 8 + warp;
    const float* xt = x + (size_t)t * D_;

    float acc[E_];
#pragma unroll
    for (int e = 0; e < E_; e++) acc[e] = 0.f;
    for (int c = 0; c < D_ / 32; c++) {
        float xv = xt[c * 32 + lane];
#pragma unroll
        for (int e = 0; e < E_; e++)
            acc[e] += xv * srw[e * D_ + c * 32 + lane];
    }
#pragma unroll
    for (int e = 0; e < E_; e++) {
#pragma unroll
        for (int off = 16; off; off >>= 1)
            acc[e] += __shfl_xor_sync(0xffffffffu, acc[e], off);
    }
    if (lane == 0) {
        int b0 = 0; float v0 = acc[0];
#pragma unroll
        for (int e = 1; e < E_; e++) if (acc[e] > v0) { v0 = acc[e]; b0 = e; }
        int b1 = -1; float v1 = -INFINITY;
#pragma unroll
        for (int e = 0; e < E_; e++) if (e != b0 && acc[e] > v1) { v1 = acc[e]; b1 = e; }
        float ex = expf(v1 - v0);
        float w0 = 1.f / (1.f + ex);
        float w1 = ex * w0;
        g_te0[t] = b0; g_te1[t] = b1;
        g_tw0[t] = w0; g_tw1[t] = w1;
        g_tslot[2 * t + 0] = -1;
        g_tslot[2 * t + 1] = -1;
    }
}

// ---------------- Dispatch (ordered capacity scan) ----------------
__global__ void __launch_bounds__(256) dispatch_kernel()
{
    int e = blockIdx.x;
    int tid = threadIdx.x;
    int lane = tid & 31, warp = tid >> 5;
    __shared__ int warpsums[8];

    for (int c = tid; c < CAP_; c += 256) { g_tokens[e * CAP_ + c] = 0; g_gates[e * CAP_ + c] = 0.f; }
    __syncthreads();

    int running = 0;
    for (int it = 0; it < T_ / 256; ++it) {
        int t = it * 256 + tid;
        int which = (g_te0[t] == e) ? 0 : ((g_te1[t] == e) ? 1 : -1);
        int flag = (which >= 0) ? 1 : 0;

        int v = flag;
#pragma unroll
        for (int off = 1; off < 32; off <<= 1) {
            int n = __shfl_up_sync(0xffffffffu, v, off);
            if (lane >= off) v += n;
        }
        if (lane == 31) warpsums[warp] = v;
        __syncthreads();

        int woff = 0, total = 0;
#pragma unroll
        for (int w = 0; w < 8; w++) {
            int s = warpsums[w];
            if (w < warp) woff += s;
            total += s;
        }
        int slot = running + woff + v - flag;
        if (flag && slot < CAP_) {
            g_tokens[e * CAP_ + slot] = t;
            g_gates [e * CAP_ + slot] = which ? g_tw1[t] : g_tw0[t];
            g_tslot[2 * t + which] = e * CAP_ + slot;
        }
        running += total;
        __syncthreads();
    }
    if (tid == 0) g_counts[e] = running;
}

// ---------------- Gather + 3-term bf16 split (A pattern h,h,l) ----------------
__global__ void __launch_bounds__(256) gather_split_kernel(const float* __restrict__ x)
{
    int row = blockIdx.x;                       // e*CAP + c
    int t = g_tokens[row];
    int tid = threadIdx.x;
    float4 v = ((const float4*)(x + (size_t)t * D_))[tid];
    float vv[4] = {v.x, v.y, v.z, v.w};
    unsigned short s[12];
#pragma unroll
    for (int j = 0; j < 4; j++) {
        __nv_bfloat16 hb = __float2bfloat16_rn(vv[j]);
        __nv_bfloat16 lb = __float2bfloat16_rn(vv[j] - __bfloat162float(hb));
        unsigned short h = __bfloat16_as_ushort(hb);
        unsigned short l = __bfloat16_as_ushort(lb);
        s[3*j] = h; s[3*j+1] = h; s[3*j+2] = l;
    }
    uint2* dst = (uint2*)(g_xg3 + (size_t)row * KP1 + 12 * tid);
    uint2 a, b, c2;
    a.x  = (uint32_t)s[0] | ((uint32_t)s[1] << 16);
    a.y  = (uint32_t)s[2] | ((uint32_t)s[3] << 16);
    b.x  = (uint32_t)s[4] | ((uint32_t)s[5] << 16);
    b.y  = (uint32_t)s[6] | ((uint32_t)s[7] << 16);
    c2.x = (uint32_t)s[8] | ((uint32_t)s[9] << 16);
    c2.y = (uint32_t)s[10]| ((uint32_t)s[11]<< 16);
    dst[0] = a; dst[1] = b; dst[2] = c2;
}

// ---------------- Weight transpose + split: [E,K,N] fp32 -> [E,N,3K] bf16 (H,L,H) ----------------
// v2: k-pair processing, aligned uint32 stores.
__global__ void __launch_bounds__(256) convert_w_kernel(
    const float* __restrict__ src, __nv_bfloat16* __restrict__ dst, int K, int N)
{
    __shared__ float tile[32][33];
    int e = blockIdx.z;
    int k0 = blockIdx.y * 32, n0 = blockIdx.x * 32;
    int tid = threadIdx.x;
    const float* se = src + (size_t)e * K * N;
    __nv_bfloat16* de = dst + (size_t)e * N * 3 * K;

#pragma unroll
    for (int j = 0; j < 4; j++) {
        int idx = tid + 256 * j;
        int r = idx >> 5, c = idx & 31;
        tile[r][c] = se[(size_t)(k0 + r) * N + n0 + c];
    }
    __syncthreads();

    int kp = tid & 15;              // k-pair index
    int nr = tid >> 4;              // 0..15
#pragma unroll
    for (int jn = 0; jn < 2; jn++) {
        int nl = nr + jn * 16;
        int n = n0 + nl;
        float v0 = tile[2 * kp][nl];
        float v1 = tile[2 * kp + 1][nl];
        __nv_bfloat16 h0b = __float2bfloat16_rn(v0);
        __nv_bfloat16 l0b = __float2bfloat16_rn(v0 - __bfloat162float(h0b));
        __nv_bfloat16 h1b = __float2bfloat16_rn(v1);
        __nv_bfloat16 l1b = __float2bfloat16_rn(v1 - __bfloat162float(h1b));
        uint32_t h0 = __bfloat16_as_ushort(h0b), l0 = __bfloat16_as_ushort(l0b);
        uint32_t h1 = __bfloat16_as_ushort(h1b), l1 = __bfloat16_as_ushort(l1b);
        uint32_t* p = (uint32_t*)(de + (size_t)n * 3 * K + (size_t)3 * (k0 + 2 * kp));
        p[0] = h0 | (l0 << 16);     // H0,L0
        p[1] = h0 | (h1 << 16);     // H0,H1
        p[2] = l1 | (h1 << 16);     // L1,H1
    }
}

// ---------------- HMMA grouped GEMM: out = act(A @ B^T + bias) ----------------
// A: [M, Kp] bf16 K-major per expert. B: [Nt, Kp] bf16 K-major per expert.
// CTA tile 128x256x64, 256 threads (8 warps 2x4), warp tile 64x64, 4-stage cp.async.
__device__ __forceinline__ float gelu_exact(float v) {
    return 0.5f * v * (1.f + erff(v * 0.70710678118654752f));
}

#define STAGE_BYTES 49152           // 16KB A + 32KB B
#define NSTAGE 4
#define SMEM_BYTES_GEMM (NSTAGE * STAGE_BYTES)   // 192 KB

template<bool GELU_SPLIT>
__global__ void __launch_bounds__(256, 1) gemm_mma_kernel(
    const __nv_bfloat16* __restrict__ A, const __nv_bfloat16* __restrict__ Bw,
    const float* __restrict__ bias, void* __restrict__ outv,
    int M, int Nt, int Kp)
{
    extern __shared__ char smem[];
    uint32_t sb = (uint32_t)__cvta_generic_to_shared(smem);

    int tid  = threadIdx.x;
    int lane = tid & 31;
    int warp = tid >> 5;
    int wm = warp >> 2, wn = warp & 3;          // 2x4 warp grid, warp tile 64x64

    int e  = blockIdx.z;
    int n0 = blockIdx.x * 256, m0 = blockIdx.y * 128;

    const char* Ae = (const char*)(A  + (size_t)e * M  * Kp + (size_t)m0 * Kp);
    const char* Be = (const char*)(Bw + (size_t)e * Nt * Kp + (size_t)n0 * Kp);
    const float* be = bias + (size_t)e * Nt;
    const size_t ld = (size_t)Kp * 2;           // row stride in bytes

    const int NCH = Kp / 64;                    // 128B chunks along K

    auto load_stage = [&](int c, int s) {
        const char* Ag = Ae + (size_t)c * 128;
        const char* Bg = Be + (size_t)c * 128;
        uint32_t Aoff = sb + s * STAGE_BYTES;
        uint32_t Boff = Aoff + 16384;
#pragma unroll
        for (int i = 0; i < 4; i++) {           // A: 128 rows x 8 x 16B
            int idx = tid + i * 256;
            int r = idx >> 3, c16 = idx & 7;
            CP_ASYNC16(Aoff + SWZ(r * 128 + c16 * 16), Ag + (size_t)r * ld + c16 * 16);
        }
#pragma unroll
        for (int i = 0; i < 8; i++) {           // B: 256 rows x 8 x 16B
            int idx = tid + i * 256;
            int r = idx >> 3, c16 = idx & 7;
            CP_ASYNC16(Boff + SWZ(r * 128 + c16 * 16), Bg + (size_t)r * ld + c16 * 16);
        }
    };

    float acc[4][8][4];
#pragma unroll
    for (int i = 0; i < 4; i++)
#pragma unroll
        for (int j = 0; j < 8; j++)
#pragma unroll
            for (int k = 0; k < 4; k++) acc[i][j][k] = 0.f;

    load_stage(0, 0); CP_COMMIT();
    load_stage(1, 1); CP_COMMIT();
    load_stage(2, 2); CP_COMMIT();

    int aRow = wm * 64 + (lane & 15);
    int bRow = wn * 64 + (lane & 15);
    int halfCol = (lane >> 4) * 16;             // 16B column offset for ldmatrix

    for (int c = 0; c < NCH; ++c) {
        CP_WAIT2();
        __syncthreads();
        if (c + 3 < NCH) load_stage(c + 3, (c + 3) & (NSTAGE - 1));
        CP_COMMIT();

        int s = c & (NSTAGE - 1);
        uint32_t Aoff = sb + s * STAGE_BYTES;
        uint32_t Boff = Aoff + 16384;

#pragma unroll
        for (int ks = 0; ks < 4; ks++) {
            uint32_t afr[4][4], bfr[4][4];
#pragma unroll
            for (int mt = 0; mt < 4; mt++) {
                uint32_t ad = Aoff + SWZ((aRow + mt * 16) * 128 + ks * 32 + halfCol);
                LDMATRIX_X4(afr[mt], ad);
            }
#pragma unroll
            for (int nt = 0; nt < 4; nt++) {
                uint32_t bd = Boff + SWZ((bRow + nt * 16) * 128 + ks * 32 + halfCol);
                LDMATRIX_X4(bfr[nt], bd);
            }
#pragma unroll
            for (int mt = 0; mt < 4; mt++)
#pragma unroll
                for (int n8 = 0; n8 < 8; n8++) {
                    int nt = n8 >> 1, j = n8 & 1;
                    MMA_16816(acc[mt][n8], afr[mt], bfr[nt][j], bfr[nt][2 + j]);
                }
        }
    }

    // -------- Epilogue --------
#pragma unroll
    for (int mt = 0; mt < 4; mt++) {
#pragma unroll
        for (int rr = 0; rr < 2; rr++) {
            int row = m0 + wm * 64 + mt * 16 + (lane >> 2) + rr * 8;
#pragma unroll
            for (int n8 = 0; n8 < 8; n8++) {
                int colL = wn * 64 + n8 * 8 + (lane & 3) * 2;
                int col  = n0 + colL;
                float v0 = acc[mt][n8][rr * 2 + 0] + be[col];
                float v1 = acc[mt][n8][rr * 2 + 1] + be[col + 1];
                if (GELU_SPLIT) {
                    v0 = gelu_exact(v0); v1 = gelu_exact(v1);
                    __nv_bfloat16 h0b = __float2bfloat16_rn(v0);
                    __nv_bfloat16 l0b = __float2bfloat16_rn(v0 - __bfloat162float(h0b));
                    __nv_bfloat16 h1b = __float2bfloat16_rn(v1);
                    __nv_bfloat16 l1b = __float2bfloat16_rn(v1 - __bfloat162float(h1b));
                    uint32_t h0 = __bfloat16_as_ushort(h0b), l0 = __bfloat16_as_ushort(l0b);
                    uint32_t h1 = __bfloat16_as_ushort(h1b), l1 = __bfloat16_as_ushort(l1b);
                    __nv_bfloat16* oe = (__nv_bfloat16*)outv
                        + (size_t)e * M * 3 * Nt + (size_t)row * 3 * Nt + (size_t)3 * col;
                    uint32_t* p = (uint32_t*)oe;        // 4B-aligned (col even)
                    p[0] = h0 | (h0 << 16);             // h0,h0
                    p[1] = l0 | (h1 << 16);             // l0,h1
                    p[2] = h1 | (l1 << 16);             // h1,l1
                } else {
                    float* oe = (float*)outv + (size_t)e * M * Nt + (size_t)row * Nt + col;
                    *(float2*)oe = make_float2(v0, v1);
                }
            }
        }
    }
}

// ---------------- Combine ----------------
__global__ void __launch_bounds__(256) combine_kernel(float* __restrict__ out)
{
    int t = blockIdx.x;
    int p0 = g_tslot[2 * t], p1 = g_tslot[2 * t + 1];
    int i = threadIdx.x;
    float4 r = make_float4(0.f, 0.f, 0.f, 0.f);
    if (p0 >= 0) {
        float w = g_gates[p0];
        float4 a = ((const float4*)(g_y + (size_t)p0 * D_))[i];
        r.x += w * a.x; r.y += w * a.y; r.z += w * a.z; r.w += w * a.w;
    }
    if (p1 >= 0) {
        float w = g_gates[p1];
        float4 a = ((const float4*)(g_y + (size_t)p1 * D_))[i];
        r.x += w * a.x; r.y += w * a.y; r.z += w * a.z; r.w += w * a.w;
    }
    ((float4*)(out + (size_t)t * D_))[i] = r;
}

// ---------------- Load-balancing loss ----------------
__global__ void loss_kernel(float* __restrict__ loss_out)
{
    if (threadIdx.x == 0) {
        const float ideal = (float)T_ * TOPK_ / E_;
        float s = 0.f;
#pragma unroll
        for (int e = 0; e < E_; e++) {
            float d = (float)g_counts[e] - ideal;
            s += d * d;
        }
        *loss_out = s / ((float)T_ * (float)T_);
    }
}

// ---------------- Launch ----------------
extern "C" void kernel_launch(void* const* d_in, const int* in_sizes, int n_in,
                              void* d_out, int out_size)
{
    const float* x  = (const float*)d_in[0];
    const float* rw = (const float*)d_in[1];
    const float* w1 = (const float*)d_in[2];
    const float* b1 = (const float*)d_in[3];
    const float* w2 = (const float*)d_in[4];
    const float* b2 = (const float*)d_in[5];
    float* out = (float*)d_out;

    __nv_bfloat16 *xg3, *w1b, *w2b, *h3; float* y;
    cudaGetSymbolAddress((void**)&xg3, g_xg3);
    cudaGetSymbolAddress((void**)&w1b, g_w1b);
    cudaGetSymbolAddress((void**)&w2b, g_w2b);
    cudaGetSymbolAddress((void**)&h3,  g_h3);
    cudaGetSymbolAddress((void**)&y,   g_y);

    cudaFuncSetAttribute(gemm_mma_kernel<true>,
                         cudaFuncAttributeMaxDynamicSharedMemorySize, SMEM_BYTES_GEMM);
    cudaFuncSetAttribute(gemm_mma_kernel<false>,
                         cudaFuncAttributeMaxDynamicSharedMemorySize, SMEM_BYTES_GEMM);

    router_kernel<<<T_ / 8, 256>>>(x, rw);
    dispatch_kernel<<<E_, 256>>>();
    gather_split_kernel<<<E_ * CAP_, 256>>>(x);
    convert_w_kernel<<<dim3(DFF_ / 32, D_ / 32, E_), 256>>>(w1, w1b, D_, DFF_);
    convert_w_kernel<<<dim3(D_ / 32, DFF_ / 32, E_), 256>>>(w2, w2b, DFF_, D_);

    gemm_mma_kernel<true><<<dim3(DFF_ / 256, CAP_ / 128, E_), 256, SMEM_BYTES_GEMM>>>(
        xg3, w1b, b1, (void*)h3, CAP_, DFF_, KP1);
    gemm_mma_kernel<false><<<dim3(D_ / 256, CAP_ / 128, E_), 256, SMEM_BYTES_GEMM>>>(
        h3, w2b, b2, (void*)y, CAP_, D_, KP2);

    combine_kernel<<<T_, 256>>>(out);
    loss_kernel<<<1, 32>>>(out + (out_size - 1));
}